// round 1
// baseline (speedup 1.0000x reference)
#include <cuda_runtime.h>

#define DIMC   512
#define BC     512
#define KC     128
#define NWARP  8
#define TPB    256
#define EPSF   1e-6f
#define MARGINF 2.0f

__device__ __forceinline__ float softplusf(float x) {
    return (x > 20.f) ? x : log1pf(expf(x));
}

__global__ __launch_bounds__(TPB)
void ultrae_kernel(const float* __restrict__ emb,
                   const float* __restrict__ rel_boost,
                   const float* __restrict__ rot_left,
                   const float* __restrict__ rot_right,
                   const float* __restrict__ bias_head,
                   const float* __restrict__ bias_tail,
                   const int*   __restrict__ u_idx,
                   const int*   __restrict__ r_idx,
                   const int*   __restrict__ v_idx,
                   float*       __restrict__ out)
{
    __shared__ __align__(16) float sh[DIMC];
    __shared__ float red[NWARP];
    __shared__ float a_sh;

    const int b    = blockIdx.x;
    const int tid  = threadIdx.x;          // pair index 0..255
    const int lane = tid & 31;
    const int warp = tid >> 5;
    const int u    = u_idx[b];
    const int r    = r_idx[b];

    // ---------------- head preprocessing (per block) ----------------
    const float* hrow = emb + (size_t)u * DIMC;
    float x0 = hrow[2 * tid];
    float x1 = hrow[2 * tid + 1];
    if (tid == 0) x0 = 0.f;                               // proj_tan0
    // a = -(u0^2+u1^2) + sum_{j>=2} u_j^2  (u0 forced 0)
    float acc = (tid == 0) ? (-x1 * x1) : (x0 * x0 + x1 * x1);
    #pragma unroll
    for (int o = 16; o; o >>= 1) acc += __shfl_xor_sync(0xffffffffu, acc, o);
    if (lane == 0) red[warp] = acc;
    __syncthreads();
    if (tid == 0) {
        float a = 0.f;
        #pragma unroll
        for (int w = 0; w < NWARP; ++w) a += red[w];
        a_sh = a;
    }
    __syncthreads();
    const float a = a_sh;

    float c, s;
    if (a > 0.f) {
        float sp = sqrtf(fmaxf(a, EPSF));
        c = coshf(sp);  s = sinhf(sp) / sp;
    } else {
        float st = sqrtf(fmaxf(-a, EPSF));
        c = cosf(st);   s = sinf(st) / st;
    }
    // expmap0: out[0] = c, out[j] = s*u_j
    float y0 = (tid == 0) ? c : s * x0;
    float y1 = s * x1;

    // givens_rotations with rot_right
    {
        float g0 = rot_right[(size_t)r * DIMC + 2 * tid];
        float g1 = rot_right[(size_t)r * DIMC + 2 * tid + 1];
        float n  = fmaxf(sqrtf(g0 * g0 + g1 * g1), 1e-15f);
        float cr = g0 / n, sr = g1 / n;
        float z0 = cr * y0 - sr * y1;
        float z1 = cr * y1 + sr * y0;
        sh[2 * tid]     = z0;
        sh[2 * tid + 1] = z1;
    }
    __syncthreads();

    // Lorentz boost: identity except entries mixing (0,510) and (1,511)
    if (tid == 0) {
        float b0 = softplusf(rel_boost[2 * r]);
        float b1 = softplusf(rel_boost[2 * r + 1]);
        float C0 = sqrtf(1.f + b0 * b0);
        float C1 = sqrtf(1.f + b1 * b1);
        float t0 = sh[0], t1 = sh[1];
        float q0 = sh[DIMC - 2], q1 = sh[DIMC - 1];
        sh[0]        = C0 * t0 - b0 * q0;
        sh[DIMC - 2] = C0 * q0 - b0 * t0;
        sh[1]        = C1 * t1 - b1 * q1;
        sh[DIMC - 1] = C1 * q1 - b1 * t1;
    }
    __syncthreads();

    // givens_reflection with rot_left (each thread owns its pair: no hazard)
    {
        float w0 = sh[2 * tid], w1 = sh[2 * tid + 1];
        float l0 = rot_left[(size_t)r * DIMC + 2 * tid];
        float l1 = rot_left[(size_t)r * DIMC + 2 * tid + 1];
        float n  = fmaxf(sqrtf(l0 * l0 + l1 * l1), 1e-15f);
        float cl = l0 / n, sl = l1 / n;
        sh[2 * tid]     = cl * w0 + sl * w1;
        sh[2 * tid + 1] = sl * w0 - cl * w1;
    }
    __syncthreads();

    const float h0 = sh[0];
    const float h1 = sh[1];
    const float nh = sqrtf(h0 * h0 + h1 * h1);
    const float hb = bias_head[u];

    // each lane keeps its 16 head dims in registers
    const float4 H0 = *(const float4*)&sh[lane * 16 + 0];
    const float4 H1 = *(const float4*)&sh[lane * 16 + 4];
    const float4 H2 = *(const float4*)&sh[lane * 16 + 8];
    const float4 H3 = *(const float4*)&sh[lane * 16 + 12];

    // ---------------- tail loop: each warp handles 16 tails ----------------
    const int kbase = warp * (KC / NWARP);
    for (int t = 0; t < KC / NWARP; ++t) {
        const int k  = kbase + t;
        const int vi = v_idx[b * KC + k];
        const float4* tp = (const float4*)(emb + (size_t)vi * DIMC) + lane * 4;
        float4 T0 = tp[0], T1 = tp[1], T2 = tp[2], T3 = tp[3];

        // full-vector accumulation
        float sq = T0.x*T0.x + T0.y*T0.y + T0.z*T0.z + T0.w*T0.w
                 + T1.x*T1.x + T1.y*T1.y + T1.z*T1.z + T1.w*T1.w
                 + T2.x*T2.x + T2.y*T2.y + T2.z*T2.z + T2.w*T2.w
                 + T3.x*T3.x + T3.y*T3.y + T3.z*T3.z + T3.w*T3.w;
        float dt = H0.x*T0.x + H0.y*T0.y + H0.z*T0.z + H0.w*T0.w
                 + H1.x*T1.x + H1.y*T1.y + H1.z*T1.z + H1.w*T1.w
                 + H2.x*T2.x + H2.y*T2.y + H2.z*T2.z + H2.w*T2.w
                 + H3.x*T3.x + H3.y*T3.y + H3.z*T3.z + H3.w*T3.w;
        float t1raw = T0.y;   // tail element 1 (raw), valid on lane 0
        if (lane == 0) {
            // a_tail = -u1^2 + sum_{j>=2} u_j^2 ; dot only over spatial dims
            sq -= T0.x * T0.x + 2.f * T0.y * T0.y;
            dt -= H0.x * T0.x + H0.y * T0.y;
        }
        #pragma unroll
        for (int o = 16; o; o >>= 1) {
            sq += __shfl_xor_sync(0xffffffffu, sq, o);
            dt += __shfl_xor_sync(0xffffffffu, dt, o);
        }
        t1raw = __shfl_sync(0xffffffffu, t1raw, 0);

        if (lane == 0) {
            float ct, stf;
            if (sq > 0.f) {
                float sp = sqrtf(fmaxf(sq, EPSF));
                ct = coshf(sp);  stf = sinhf(sp) / sp;
            } else {
                float st = sqrtf(fmaxf(-sq, EPSF));
                ct = cosf(st);   stf = sinf(st) / st;
            }
            float ty0 = ct;              // tail time comp 0 (u0=0 -> c)
            float ty1 = stf * t1raw;     // tail time comp 1
            float nt  = sqrtf(ty0 * ty0 + ty1 * ty1);
            float dxy = stf * dt;        // dot(xs, ys) = s_t * sum h_j u_j

            float cosang = (h0 * ty0 + h1 * ty1) / (nh * nt);
            cosang = fminf(fmaxf(cosang, -1.f + EPSF), 1.f - EPSF);
            float theta = acosf(cosang);

            float inner = nh * nt - dxy;
            float dh = acoshf(fmaxf(inner, 1.f + EPSF));

            float d1 = nh * theta + dh;
            float d2 = nt * theta + dh;
            float dist = fminf(d1 * d1, d2 * d2);

            out[b * KC + k] = MARGINF - dist + hb + bias_tail[vi];
        }
    }
}

extern "C" void kernel_launch(void* const* d_in, const int* in_sizes, int n_in,
                              void* d_out, int out_size)
{
    const float* emb       = (const float*)d_in[0];
    const float* rel_boost = (const float*)d_in[1];
    const float* rot_left  = (const float*)d_in[2];
    const float* rot_right = (const float*)d_in[3];
    const float* bias_head = (const float*)d_in[4];
    const float* bias_tail = (const float*)d_in[5];
    const int*   u_idx     = (const int*)d_in[6];
    const int*   r_idx     = (const int*)d_in[7];
    const int*   v_idx     = (const int*)d_in[8];

    ultrae_kernel<<<BC, TPB>>>(emb, rel_boost, rot_left, rot_right,
                               bias_head, bias_tail, u_idx, r_idx, v_idx,
                               (float*)d_out);
}